// round 1
// baseline (speedup 1.0000x reference)
#include <cuda_runtime.h>
#include <cuda_bf16.h>

// y = (x + 2) * 3 / 2  ==  1.5f * x + 3.0f   (single FMA, exact in fp32:
//   (x+2)*3/2: fp32 ops (x+2), *3, /2 — note /2 is exact, *3 exact when no
//   rounding... to be safe against rel_err 1e-3 we can compute either way;
//   1.5*x + 3 differs from ((x+2)*3)*0.5 by at most ~2 ulp, far below 1e-3.)
//
// HBM-bound streaming kernel: float4 vectorized grid-stride loop.

__global__ void __launch_bounds__(256) fma_stream_kernel(
    const float4* __restrict__ in, float4* __restrict__ out, long long n4)
{
    long long i = (long long)blockIdx.x * blockDim.x + threadIdx.x;
    long long stride = (long long)gridDim.x * blockDim.x;
    for (; i < n4; i += stride) {
        float4 v = in[i];
        float4 r;
        r.x = fmaf(1.5f, v.x, 3.0f);
        r.y = fmaf(1.5f, v.y, 3.0f);
        r.z = fmaf(1.5f, v.z, 3.0f);
        r.w = fmaf(1.5f, v.w, 3.0f);
        out[i] = r;
    }
}

// Tail handler for element counts not divisible by 4 (not needed for 8192^2,
// but keeps the kernel correct for any size).
__global__ void fma_tail_kernel(const float* __restrict__ in,
                                float* __restrict__ out,
                                long long start, long long n)
{
    long long i = start + blockIdx.x * blockDim.x + threadIdx.x;
    if (i < n) out[i] = fmaf(1.5f, in[i], 3.0f);
}

extern "C" void kernel_launch(void* const* d_in, const int* in_sizes, int n_in,
                              void* d_out, int out_size)
{
    const float* in = (const float*)d_in[0];
    float* out = (float*)d_out;
    long long n = (long long)in_sizes[0];

    long long n4 = n / 4;
    if (n4 > 0) {
        int threads = 256;
        // ~8 float4 per thread per wave target: enough blocks for full
        // occupancy + MLP, grid-stride covers the rest.
        long long want_blocks = (n4 + threads - 1) / threads;
        int blocks = (int)((want_blocks > 65536) ? 65536 : want_blocks);
        fma_stream_kernel<<<blocks, threads>>>(
            (const float4*)in, (float4*)out, n4);
    }
    long long tail_start = n4 * 4;
    long long tail = n - tail_start;
    if (tail > 0) {
        fma_tail_kernel<<<(unsigned)((tail + 255) / 256), 256>>>(
            in, out, tail_start, n);
    }
}

// round 2
// speedup vs baseline: 1.0523x; 1.0523x over previous
#include <cuda_runtime.h>
#include <cuda_bf16.h>

// y = (x + 2) * 3 / 2 == fmaf(1.5f, x, 3.0f)
// HBM-bound streaming kernel. Optimizations vs R1:
//  - 8 float4 per thread, loads front-batched (MLP_p1=8)
//  - 32-bit index arithmetic
//  - streaming cache hints (no reuse; 512MB > L2)

constexpr int VPT = 8;        // float4 per thread
constexpr int THREADS = 256;
constexpr int TILE = VPT * THREADS;   // float4 per block = 2048

__global__ void __launch_bounds__(THREADS) fma_stream_kernel(
    const float4* __restrict__ in, float4* __restrict__ out)
{
    unsigned base = blockIdx.x * TILE + threadIdx.x;

    float4 v[VPT];
#pragma unroll
    for (int k = 0; k < VPT; k++)
        v[k] = __ldcs(in + base + k * THREADS);

#pragma unroll
    for (int k = 0; k < VPT; k++) {
        float4 r;
        r.x = fmaf(1.5f, v[k].x, 3.0f);
        r.y = fmaf(1.5f, v[k].y, 3.0f);
        r.z = fmaf(1.5f, v[k].z, 3.0f);
        r.w = fmaf(1.5f, v[k].w, 3.0f);
        __stcs(out + base + k * THREADS, r);
    }
}

// Generic remainder kernel (element granularity, any size).
__global__ void fma_tail_kernel(const float* __restrict__ in,
                                float* __restrict__ out,
                                long long start, long long n)
{
    long long i = start + (long long)blockIdx.x * blockDim.x + threadIdx.x;
    if (i < n) out[i] = fmaf(1.5f, in[i], 3.0f);
}

extern "C" void kernel_launch(void* const* d_in, const int* in_sizes, int n_in,
                              void* d_out, int out_size)
{
    const float* in = (const float*)d_in[0];
    float* out = (float*)d_out;
    long long n = (long long)in_sizes[0];

    long long n4 = n / 4;
    long long full_blocks = n4 / TILE;          // blocks covering TILE float4s each
    if (full_blocks > 0) {
        fma_stream_kernel<<<(unsigned)full_blocks, THREADS>>>(
            (const float4*)in, (float4*)out);
    }
    long long done = full_blocks * (long long)TILE * 4;  // elements handled
    long long tail = n - done;
    if (tail > 0) {
        fma_tail_kernel<<<(unsigned)((tail + 255) / 256), 256>>>(
            in, out, done, n);
    }
}